// round 4
// baseline (speedup 1.0000x reference)
#include <cuda_runtime.h>
#include <math.h>

// Problem constants
#define NB 8
#define NN 2048
#define NC 128
#define NCH 64      // chunks per batch
#define CSZ 32      // chunk size (NCH*CSZ == NN)
#define NP (NN+1)   // prefix length 2049

// ---------------- scratch (device globals; no allocation) ----------------
__device__ float g_h[NB*NN*NC];        // h = text @ W
__device__ float g_s1[NB*NN];
__device__ float g_s2[NB*NN];
__device__ float g_s2s[NB*NN];         // sorted s2 (ascending)
__device__ int   g_perm[NB*NN];        // permutation of sort
__device__ float g_wA[NB*NN];          // e^{s2s - m2}
__device__ float g_wB[NB*NN];          // e^{0.2(s2s - m2)}
__device__ float g_m2[NB];
__device__ float g_chA[NB*NCH*NC];     // per-chunk sums of wA*h
__device__ float g_chB[NB*NCH*NC];     // per-chunk sums of wB*h
__device__ float g_paf[NB*NP];         // full scalar exclusive prefix of wA; [2048]=total
__device__ float g_pbf[NB*NP];
__device__ float2 g_P[NB*NP*NC];       // packed full vector prefixes (x=A, y=B)

// ---------------- f32x2 packed-FMA helpers (sm_103a FFMA2) ----------------
__device__ __forceinline__ unsigned long long pack2(float x, float y) {
    unsigned long long r;
    asm("mov.b64 %0, {%1, %2};" : "=l"(r) : "f"(x), "f"(y));
    return r;
}
__device__ __forceinline__ void unpack2(unsigned long long v, float& x, float& y) {
    asm("mov.b64 {%0, %1}, %2;" : "=f"(x), "=f"(y) : "l"(v));
}
__device__ __forceinline__ void ffma2(unsigned long long& d, unsigned long long a, unsigned long long b) {
    asm("fma.rn.f32x2 %0, %1, %2, %0;" : "+l"(d) : "l"(a), "l"(b));
}

// ---------------- Kernel 1: GEMM h = text@W (f32x2), fused s1/s2 ----------------
__global__ void __launch_bounds__(256) gemm_kernel(const float* __restrict__ A,
                                                   const float* __restrict__ W,
                                                   const float* __restrict__ avec)
{
    __shared__ float As[16][64];
    __shared__ float Bs[16][128];
    const int b  = blockIdx.y;
    const int m0 = blockIdx.x * 64;
    const int tid = threadIdx.x;
    const int tx = tid & 31;          // N dir: 32 * 4 = 128
    const int ty = tid >> 5;          // M dir: 8 * 8 = 64
    const float* Ab = A + (size_t)(b*NN + m0) * NC;

    unsigned long long acc2[4][4];
#pragma unroll
    for (int p = 0; p < 4; p++)
#pragma unroll
        for (int j = 0; j < 4; j++) acc2[p][j] = 0ull;

    const int ar = tid >> 2;          // 0..63
    const int ac = (tid & 3) * 4;     // 0,4,8,12

    for (int k0 = 0; k0 < 128; k0 += 16) {
        float4 av = *(const float4*)(Ab + (size_t)ar*NC + k0 + ac);
        As[ac+0][ar] = av.x; As[ac+1][ar] = av.y;
        As[ac+2][ar] = av.z; As[ac+3][ar] = av.w;
#pragma unroll
        for (int it = 0; it < 2; it++) {
            int idx = tid + 256*it;
            int brr = idx >> 5, bcc = (idx & 31) * 4;
            *(float4*)&Bs[brr][bcc] = *(const float4*)(W + (size_t)(k0+brr)*NC + bcc);
        }
        __syncthreads();
#pragma unroll
        for (int kk = 0; kk < 16; kk++) {
            float4 a03 = *(const float4*)&As[kk][ty*8];
            float4 a47 = *(const float4*)&As[kk][ty*8 + 4];
            float4 bv  = *(const float4*)&Bs[kk][tx*4];
            unsigned long long ap[4];
            ap[0] = pack2(a03.x, a03.y); ap[1] = pack2(a03.z, a03.w);
            ap[2] = pack2(a47.x, a47.y); ap[3] = pack2(a47.z, a47.w);
            unsigned long long bd[4];
            bd[0] = pack2(bv.x, bv.x); bd[1] = pack2(bv.y, bv.y);
            bd[2] = pack2(bv.z, bv.z); bd[3] = pack2(bv.w, bv.w);
#pragma unroll
            for (int p = 0; p < 4; p++)
#pragma unroll
                for (int j = 0; j < 4; j++) ffma2(acc2[p][j], ap[p], bd[j]);
        }
        __syncthreads();
    }

    float acc[8][4];
#pragma unroll
    for (int p = 0; p < 4; p++)
#pragma unroll
        for (int j = 0; j < 4; j++) unpack2(acc2[p][j], acc[2*p][j], acc[2*p+1][j]);

    float a1[4], a2[4];
#pragma unroll
    for (int j = 0; j < 4; j++) { a1[j] = avec[tx*4+j]; a2[j] = avec[128 + tx*4+j]; }

#pragma unroll
    for (int i = 0; i < 8; i++) {
        int row = m0 + ty*8 + i;
        float4 v = make_float4(acc[i][0], acc[i][1], acc[i][2], acc[i][3]);
        *(float4*)(g_h + (size_t)(b*NN + row)*NC + tx*4) = v;
        float d1 = acc[i][0]*a1[0] + acc[i][1]*a1[1] + acc[i][2]*a1[2] + acc[i][3]*a1[3];
        float d2 = acc[i][0]*a2[0] + acc[i][1]*a2[1] + acc[i][2]*a2[2] + acc[i][3]*a2[3];
#pragma unroll
        for (int off = 16; off > 0; off >>= 1) {
            d1 += __shfl_down_sync(0xffffffffu, d1, off);
            d2 += __shfl_down_sync(0xffffffffu, d2, off);
        }
        if (tx == 0) { g_s1[b*NN + row] = d1; g_s2[b*NN + row] = d2; }
    }
}

// ---------------- Kernel 2: per-batch bitonic sort + weights + scalar prefixes ----------------
__global__ void __launch_bounds__(1024) sort_kernel()
{
    __shared__ float key[NN];
    __shared__ int   idx[NN];
    __shared__ float csA[NCH], csB[NCH];
    __shared__ float cpA[NCH+1], cpB[NCH+1];
    const int b = blockIdx.x, tid = threadIdx.x;

    for (int i = tid; i < NN; i += 1024) { key[i] = g_s2[b*NN + i]; idx[i] = i; }
    __syncthreads();

    for (int k2 = 2; k2 <= NN; k2 <<= 1) {
        for (int j = k2 >> 1; j > 0; j >>= 1) {
            for (int i = tid; i < NN; i += 1024) {
                int ixj = i ^ j;
                if (ixj > i) {
                    bool up = ((i & k2) == 0);
                    float ka = key[i], kb = key[ixj];
                    bool sw = up ? (ka > kb) : (ka < kb);
                    if (sw) {
                        key[i] = kb; key[ixj] = ka;
                        int t = idx[i]; idx[i] = idx[ixj]; idx[ixj] = t;
                    }
                }
            }
            __syncthreads();
        }
    }

    float m2v = key[NN-1];
    if (tid == 0) g_m2[b] = m2v;

    float wa[2], wb[2];
#pragma unroll
    for (int u = 0; u < 2; u++) {
        int i = tid + 1024*u;
        float s = key[i] - m2v;
        wa[u] = expf(s);
        wb[u] = expf(0.2f * s);
        g_s2s[b*NN + i]  = key[i];
        g_perm[b*NN + i] = idx[i];
        g_wA[b*NN + i]   = wa[u];
        g_wB[b*NN + i]   = wb[u];
    }
    __syncthreads();
    float* fidx = (float*)idx;   // reuse idx storage for wB
#pragma unroll
    for (int u = 0; u < 2; u++) {
        int i = tid + 1024*u;
        key[i]  = wa[u];
        fidx[i] = wb[u];
    }
    __syncthreads();
    if (tid < NCH) {
        float ca = 0.f, cb = 0.f;
#pragma unroll 8
        for (int r = 0; r < CSZ; r++) { ca += key[tid*CSZ + r]; cb += fidx[tid*CSZ + r]; }
        csA[tid] = ca; csB[tid] = cb;
    }
    __syncthreads();
    if (tid == 0) {
        float ra = 0.f, rb = 0.f;
        for (int c = 0; c < NCH; c++) {
            cpA[c] = ra; cpB[c] = rb;
            ra += csA[c]; rb += csB[c];
        }
        cpA[NCH] = ra; cpB[NCH] = rb;
        g_paf[b*NP + NN] = ra; g_pbf[b*NP + NN] = rb;
    }
    __syncthreads();
    if (tid < NCH) {
        float ra = cpA[tid], rb = cpB[tid];
#pragma unroll 8
        for (int r = 0; r < CSZ; r++) {
            int i = tid*CSZ + r;
            g_paf[b*NP + i] = ra; g_pbf[b*NP + i] = rb;
            ra += key[i]; rb += fidx[i];
        }
    }
}

// ---------------- Kernel 3: vector chunk sums (per chunk) ----------------
__global__ void __launch_bounds__(128) chunk_kernel()
{
    __shared__ int   js[CSZ];
    __shared__ float swa[CSZ], swb[CSZ];
    const int b = blockIdx.y, c = blockIdx.x, f = threadIdx.x;
    const int base = b*NN + c*CSZ;
    if (f < CSZ) {
        js[f]  = g_perm[base + f];
        swa[f] = g_wA[base + f];
        swb[f] = g_wB[base + f];
    }
    __syncthreads();
    float aA = 0.f, aB = 0.f;
#pragma unroll
    for (int r = 0; r < CSZ; r++) {
        float hv = g_h[(size_t)(b*NN + js[r])*NC + f];
        aA = fmaf(swa[r], hv, aA);
        aB = fmaf(swb[r], hv, aB);
    }
    g_chA[(size_t)(b*NCH+c)*NC + f] = aA;
    g_chB[(size_t)(b*NCH+c)*NC + f] = aB;
}

// ---------------- Kernel 4: expand full vector prefixes (MLP'd chunk-prefix) ----------------
__global__ void __launch_bounds__(128) expand_kernel()
{
    __shared__ float wa[CSZ], wb[CSZ];
    __shared__ int js[CSZ];
    const int b = blockIdx.y, c = blockIdx.x, f = threadIdx.x;
    const int base = b*NN + c*CSZ;
    if (f < CSZ) {
        wa[f] = g_wA[base + f];
        wb[f] = g_wB[base + f];
        js[f] = g_perm[base + f];
    }
    __syncthreads();

    // exclusive chunk base: unrolled-by-8, 8 independent accumulator streams per array
    const size_t chbase = (size_t)(b*NCH)*NC + f;
    float aA[8], aB[8];
#pragma unroll
    for (int u = 0; u < 8; u++) { aA[u] = 0.f; aB[u] = 0.f; }
    int cp = 0;
    for (; cp + 8 <= c; cp += 8) {
#pragma unroll
        for (int u = 0; u < 8; u++) {
            aA[u] += g_chA[chbase + (size_t)(cp+u)*NC];
            aB[u] += g_chB[chbase + (size_t)(cp+u)*NC];
        }
    }
    for (; cp < c; cp++) {
        aA[cp & 7] += g_chA[chbase + (size_t)cp*NC];
        aB[cp & 7] += g_chB[chbase + (size_t)cp*NC];
    }
    float runA = ((aA[0]+aA[1])+(aA[2]+aA[3])) + ((aA[4]+aA[5])+(aA[6]+aA[7]));
    float runB = ((aB[0]+aB[1])+(aB[2]+aB[3])) + ((aB[4]+aB[5])+(aB[6]+aB[7]));

    size_t p = (size_t)(b*NP + c*CSZ)*NC + f;
#pragma unroll
    for (int r = 0; r < CSZ; r++) {
        g_P[p] = make_float2(runA, runB);
        float hv = g_h[(size_t)(b*NN + js[r])*NC + f];
        runA = fmaf(wa[r], hv, runA);
        runB = fmaf(wb[r], hv, runB);
        p += NC;
    }
    if (c == NCH-1) g_P[p] = make_float2(runA, runB);  // index NN: grand totals
}

// ---------------- Kernel 5: per-query output ----------------
__global__ void __launch_bounds__(128) query_kernel(float* __restrict__ out)
{
    __shared__ float s2sh[NN];
    __shared__ int   ks[16];
    __shared__ float s1s[16];
    const int b = blockIdx.y, f = threadIdx.x;
    const int qbase = blockIdx.x * 16;
    for (int i = f; i < NN; i += 128) s2sh[i] = g_s2s[b*NN + i];
    __syncthreads();

    if (f < 16) {
        const int i = qbase + f;
        const float s1v = g_s1[b*NN + i];
        s1s[f] = s1v;
        const float t = -s1v;
        int k = 0;
#pragma unroll
        for (int st = 2048; st > 0; st >>= 1) {
            int nk = k + st;
            if (nk <= NN && s2sh[nk-1] <= t) k = nk;
        }
        ks[f] = k;
    }
    __syncthreads();

    const float m2v = g_m2[b];
    const float taf = g_P[(size_t)(b*NP + NN)*NC + f].x;
    const float tas = g_paf[b*NP + NN];

#pragma unroll 4
    for (int qi = 0; qi < 16; qi++) {
        const int i = qbase + qi;
        const int k = ks[qi];
        const float s1v = s1s[qi];
        const float2 Pk = g_P[(size_t)(b*NP + k)*NC + f];
        const float sap = g_paf[b*NP + k];
        const float sbp = g_pbf[b*NP + k];
        const float SA = taf - Pk.x, SB = Pk.y;
        const float sa = tas - sap, sb = sbp;
        const float u = s1v + m2v;
        float hp;
        if (u > 0.f) {
            float inv = expf(-0.8f * u);
            hp = (SA + inv*SB) / (sa + inv*sb);
        } else {
            float fc = expf(0.8f * u);
            hp = (fc*SA + SB) / (fc*sa + sb);
        }
        const float hvi = g_h[(size_t)(b*NN + i)*NC + f];
        const float x = hp + 0.2f * hvi;
        out[(size_t)(b*NN + i)*NC + f] = (x > 0.f) ? x : expm1f(x);
    }
}

// ---------------- launch ----------------
extern "C" void kernel_launch(void* const* d_in, const int* in_sizes, int n_in,
                              void* d_out, int out_size)
{
    int iText = 0, iW = 2, iA = 3;
    for (int i = 0; i < n_in; i++) {
        if (in_sizes[i] == NB*NN*NC) iText = i;
        else if (in_sizes[i] == NC*NC) iW = i;
        else if (in_sizes[i] == 2*NC) iA = i;
    }
    const float* text = (const float*)d_in[iText];
    const float* W    = (const float*)d_in[iW];
    const float* avec = (const float*)d_in[iA];
    float* out = (float*)d_out;

    gemm_kernel<<<dim3(NN/64, NB), 256>>>(text, W, avec);
    sort_kernel<<<NB, 1024>>>();
    chunk_kernel<<<dim3(NCH, NB), 128>>>();
    expand_kernel<<<dim3(NCH, NB), 128>>>();
    query_kernel<<<dim3(NN/16, NB), 128>>>(out);
}

// round 5
// speedup vs baseline: 1.1333x; 1.1333x over previous
#include <cuda_runtime.h>
#include <math.h>

// Problem constants
#define NB 8
#define NN 2048
#define NC 128
#define NCH 128     // chunks per batch
#define CSZ 16      // chunk size (NCH*CSZ == NN)
#define NP (NN+1)   // prefix length 2049

// ---------------- scratch (device globals; no allocation) ----------------
__device__ float g_h[NB*NN*NC];        // h = text @ W
__device__ float g_s1[NB*NN];
__device__ float g_s2[NB*NN];
__device__ float g_s2s[NB*NN];         // sorted s2 (ascending)
__device__ int   g_perm[NB*NN];        // permutation of sort
__device__ float g_wA[NB*NN];          // e^{s2s - m2}
__device__ float g_wB[NB*NN];          // e^{0.2(s2s - m2)}
__device__ float g_m2[NB];
__device__ float2 g_ch[NB*(NCH+1)*NC]; // chunk sums (x=A,y=B) -> exclusive prefixes; [NCH]=total
__device__ float g_paf[NB*NP];         // full scalar exclusive prefix of wA; [2048]=total
__device__ float g_pbf[NB*NP];
__device__ float2 g_P[NB*NP*NC];       // packed full vector prefixes (x=A, y=B)

// ---------------- f32x2 packed-FMA helpers (sm_103a FFMA2) ----------------
__device__ __forceinline__ unsigned long long pack2(float x, float y) {
    unsigned long long r;
    asm("mov.b64 %0, {%1, %2};" : "=l"(r) : "f"(x), "f"(y));
    return r;
}
__device__ __forceinline__ void unpack2(unsigned long long v, float& x, float& y) {
    asm("mov.b64 {%0, %1}, %2;" : "=f"(x), "=f"(y) : "l"(v));
}
__device__ __forceinline__ void ffma2(unsigned long long& d, unsigned long long a, unsigned long long b) {
    asm("fma.rn.f32x2 %0, %1, %2, %0;" : "+l"(d) : "l"(a), "l"(b));
}

// ---------------- Kernel 1: GEMM h = text@W (f32x2), fused s1/s2 ----------------
__global__ void __launch_bounds__(256) gemm_kernel(const float* __restrict__ A,
                                                   const float* __restrict__ W,
                                                   const float* __restrict__ avec)
{
    __shared__ float As[16][64];
    __shared__ float Bs[16][128];
    const int b  = blockIdx.y;
    const int m0 = blockIdx.x * 64;
    const int tid = threadIdx.x;
    const int tx = tid & 31;          // N dir: 32 * 4 = 128
    const int ty = tid >> 5;          // M dir: 8 * 8 = 64
    const float* Ab = A + (size_t)(b*NN + m0) * NC;

    unsigned long long acc2[4][4];
#pragma unroll
    for (int p = 0; p < 4; p++)
#pragma unroll
        for (int j = 0; j < 4; j++) acc2[p][j] = 0ull;

    const int ar = tid >> 2;          // 0..63
    const int ac = (tid & 3) * 4;     // 0,4,8,12

    for (int k0 = 0; k0 < 128; k0 += 16) {
        float4 av = *(const float4*)(Ab + (size_t)ar*NC + k0 + ac);
        As[ac+0][ar] = av.x; As[ac+1][ar] = av.y;
        As[ac+2][ar] = av.z; As[ac+3][ar] = av.w;
#pragma unroll
        for (int it = 0; it < 2; it++) {
            int idx = tid + 256*it;
            int brr = idx >> 5, bcc = (idx & 31) * 4;
            *(float4*)&Bs[brr][bcc] = *(const float4*)(W + (size_t)(k0+brr)*NC + bcc);
        }
        __syncthreads();
#pragma unroll
        for (int kk = 0; kk < 16; kk++) {
            float4 a03 = *(const float4*)&As[kk][ty*8];
            float4 a47 = *(const float4*)&As[kk][ty*8 + 4];
            float4 bv  = *(const float4*)&Bs[kk][tx*4];
            unsigned long long ap[4];
            ap[0] = pack2(a03.x, a03.y); ap[1] = pack2(a03.z, a03.w);
            ap[2] = pack2(a47.x, a47.y); ap[3] = pack2(a47.z, a47.w);
            unsigned long long bd[4];
            bd[0] = pack2(bv.x, bv.x); bd[1] = pack2(bv.y, bv.y);
            bd[2] = pack2(bv.z, bv.z); bd[3] = pack2(bv.w, bv.w);
#pragma unroll
            for (int p = 0; p < 4; p++)
#pragma unroll
                for (int j = 0; j < 4; j++) ffma2(acc2[p][j], ap[p], bd[j]);
        }
        __syncthreads();
    }

    float acc[8][4];
#pragma unroll
    for (int p = 0; p < 4; p++)
#pragma unroll
        for (int j = 0; j < 4; j++) unpack2(acc2[p][j], acc[2*p][j], acc[2*p+1][j]);

    float a1[4], a2[4];
#pragma unroll
    for (int j = 0; j < 4; j++) { a1[j] = avec[tx*4+j]; a2[j] = avec[128 + tx*4+j]; }

#pragma unroll
    for (int i = 0; i < 8; i++) {
        int row = m0 + ty*8 + i;
        float4 v = make_float4(acc[i][0], acc[i][1], acc[i][2], acc[i][3]);
        *(float4*)(g_h + (size_t)(b*NN + row)*NC + tx*4) = v;
        float d1 = acc[i][0]*a1[0] + acc[i][1]*a1[1] + acc[i][2]*a1[2] + acc[i][3]*a1[3];
        float d2 = acc[i][0]*a2[0] + acc[i][1]*a2[1] + acc[i][2]*a2[2] + acc[i][3]*a2[3];
#pragma unroll
        for (int off = 16; off > 0; off >>= 1) {
            d1 += __shfl_down_sync(0xffffffffu, d1, off);
            d2 += __shfl_down_sync(0xffffffffu, d2, off);
        }
        if (tx == 0) { g_s1[b*NN + row] = d1; g_s2[b*NN + row] = d2; }
    }
}

// ---------------- Kernel 2: per-batch bitonic sort + weights + scalar prefixes ----------------
__global__ void __launch_bounds__(1024) sort_kernel()
{
    __shared__ float key[NN];
    __shared__ int   idx[NN];
    __shared__ float csA[NCH], csB[NCH];
    __shared__ float cpA[NCH+1], cpB[NCH+1];
    const int b = blockIdx.x, tid = threadIdx.x;

    for (int i = tid; i < NN; i += 1024) { key[i] = g_s2[b*NN + i]; idx[i] = i; }
    __syncthreads();

    for (int k2 = 2; k2 <= NN; k2 <<= 1) {
        for (int j = k2 >> 1; j > 0; j >>= 1) {
            for (int i = tid; i < NN; i += 1024) {
                int ixj = i ^ j;
                if (ixj > i) {
                    bool up = ((i & k2) == 0);
                    float ka = key[i], kb = key[ixj];
                    bool sw = up ? (ka > kb) : (ka < kb);
                    if (sw) {
                        key[i] = kb; key[ixj] = ka;
                        int t = idx[i]; idx[i] = idx[ixj]; idx[ixj] = t;
                    }
                }
            }
            __syncthreads();
        }
    }

    float m2v = key[NN-1];
    if (tid == 0) g_m2[b] = m2v;

    float wa[2], wb[2];
#pragma unroll
    for (int u = 0; u < 2; u++) {
        int i = tid + 1024*u;
        float s = key[i] - m2v;
        wa[u] = expf(s);
        wb[u] = expf(0.2f * s);
        g_s2s[b*NN + i]  = key[i];
        g_perm[b*NN + i] = idx[i];
        g_wA[b*NN + i]   = wa[u];
        g_wB[b*NN + i]   = wb[u];
    }
    __syncthreads();
    float* fidx = (float*)idx;   // reuse idx storage for wB
#pragma unroll
    for (int u = 0; u < 2; u++) {
        int i = tid + 1024*u;
        key[i]  = wa[u];
        fidx[i] = wb[u];
    }
    __syncthreads();
    if (tid < NCH) {
        float ca = 0.f, cb = 0.f;
#pragma unroll
        for (int r = 0; r < CSZ; r++) { ca += key[tid*CSZ + r]; cb += fidx[tid*CSZ + r]; }
        csA[tid] = ca; csB[tid] = cb;
    }
    __syncthreads();
    if (tid == 0) {
        float ra = 0.f, rb = 0.f;
        for (int c = 0; c < NCH; c++) {
            cpA[c] = ra; cpB[c] = rb;
            ra += csA[c]; rb += csB[c];
        }
        cpA[NCH] = ra; cpB[NCH] = rb;
        g_paf[b*NP + NN] = ra; g_pbf[b*NP + NN] = rb;
    }
    __syncthreads();
    if (tid < NCH) {
        float ra = cpA[tid], rb = cpB[tid];
#pragma unroll
        for (int r = 0; r < CSZ; r++) {
            int i = tid*CSZ + r;
            g_paf[b*NP + i] = ra; g_pbf[b*NP + i] = rb;
            ra += key[i]; rb += fidx[i];
        }
    }
}

// ---------------- Kernel 3: vector chunk sums (per chunk, packed float2) ----------------
__global__ void __launch_bounds__(128) chunk_kernel()
{
    __shared__ int   js[CSZ];
    __shared__ float swa[CSZ], swb[CSZ];
    const int b = blockIdx.y, c = blockIdx.x, f = threadIdx.x;
    const int base = b*NN + c*CSZ;
    if (f < CSZ) {
        js[f]  = g_perm[base + f];
        swa[f] = g_wA[base + f];
        swb[f] = g_wB[base + f];
    }
    __syncthreads();
    float aA = 0.f, aB = 0.f;
#pragma unroll
    for (int r = 0; r < CSZ; r++) {
        float hv = g_h[(size_t)(b*NN + js[r])*NC + f];
        aA = fmaf(swa[r], hv, aA);
        aB = fmaf(swb[r], hv, aB);
    }
    g_ch[(size_t)(b*(NCH+1)+c)*NC + f] = make_float2(aA, aB);
}

// ---------------- Kernel 4: warp-parallel exclusive scan over 128 chunks ----------------
// grid (NB, 16), 256 threads = 8 warps; warp w handles feature f = by*8 + w
// each lane owns 4 consecutive chunks
__global__ void __launch_bounds__(256) scan_kernel()
{
    const int b = blockIdx.x;
    const int w = threadIdx.x >> 5, lane = threadIdx.x & 31;
    const int f = blockIdx.y * 8 + w;
    const size_t base = (size_t)(b*(NCH+1))*NC + f;

    float2 v[4];
#pragma unroll
    for (int u = 0; u < 4; u++) v[u] = g_ch[base + (size_t)(lane*4+u)*NC];

    float ownA = (v[0].x + v[1].x) + (v[2].x + v[3].x);
    float ownB = (v[0].y + v[1].y) + (v[2].y + v[3].y);
    float sA = ownA, sB = ownB;
#pragma unroll
    for (int off = 1; off < 32; off <<= 1) {
        float nA = __shfl_up_sync(0xffffffffu, sA, off);
        float nB = __shfl_up_sync(0xffffffffu, sB, off);
        if (lane >= off) { sA += nA; sB += nB; }
    }
    float eA = sA - ownA, eB = sB - ownB;
#pragma unroll
    for (int u = 0; u < 4; u++) {
        float2 cur = v[u];
        g_ch[base + (size_t)(lane*4+u)*NC] = make_float2(eA, eB);
        eA += cur.x; eB += cur.y;
    }
    if (lane == 31) g_ch[base + (size_t)NCH*NC] = make_float2(sA, sB);
}

// ---------------- Kernel 5: expand full vector prefixes ----------------
__global__ void __launch_bounds__(128) expand_kernel()
{
    __shared__ float wa[CSZ], wb[CSZ];
    __shared__ int js[CSZ];
    const int b = blockIdx.y, c = blockIdx.x, f = threadIdx.x;
    const int base = b*NN + c*CSZ;
    if (f < CSZ) {
        wa[f] = g_wA[base + f];
        wb[f] = g_wB[base + f];
        js[f] = g_perm[base + f];
    }
    __syncthreads();

    float2 run = g_ch[(size_t)(b*(NCH+1)+c)*NC + f];
    float runA = run.x, runB = run.y;

    size_t p = (size_t)(b*NP + c*CSZ)*NC + f;
#pragma unroll
    for (int r = 0; r < CSZ; r++) {
        g_P[p] = make_float2(runA, runB);
        float hv = g_h[(size_t)(b*NN + js[r])*NC + f];
        runA = fmaf(wa[r], hv, runA);
        runB = fmaf(wb[r], hv, runB);
        p += NC;
    }
    if (c == NCH-1) g_P[p] = make_float2(runA, runB);  // index NN: grand totals
}

// ---------------- Kernel 6: per-query output ----------------
__global__ void __launch_bounds__(128) query_kernel(float* __restrict__ out)
{
    __shared__ float s2sh[NN];
    __shared__ int   ks[16];
    __shared__ float s1s[16];
    const int b = blockIdx.y, f = threadIdx.x;
    const int qbase = blockIdx.x * 16;
    for (int i = f; i < NN; i += 128) s2sh[i] = g_s2s[b*NN + i];
    __syncthreads();

    if (f < 16) {
        const int i = qbase + f;
        const float s1v = g_s1[b*NN + i];
        s1s[f] = s1v;
        const float t = -s1v;
        int k = 0;
#pragma unroll
        for (int st = 2048; st > 0; st >>= 1) {
            int nk = k + st;
            if (nk <= NN && s2sh[nk-1] <= t) k = nk;
        }
        ks[f] = k;
    }
    __syncthreads();

    const float m2v = g_m2[b];
    const float taf = g_P[(size_t)(b*NP + NN)*NC + f].x;
    const float tas = g_paf[b*NP + NN];

#pragma unroll 4
    for (int qi = 0; qi < 16; qi++) {
        const int i = qbase + qi;
        const int k = ks[qi];
        const float s1v = s1s[qi];
        const float2 Pk = g_P[(size_t)(b*NP + k)*NC + f];
        const float sap = g_paf[b*NP + k];
        const float sbp = g_pbf[b*NP + k];
        const float SA = taf - Pk.x, SB = Pk.y;
        const float sa = tas - sap, sb = sbp;
        const float u = s1v + m2v;
        float hp;
        if (u > 0.f) {
            float inv = expf(-0.8f * u);
            hp = (SA + inv*SB) / (sa + inv*sb);
        } else {
            float fc = expf(0.8f * u);
            hp = (fc*SA + SB) / (fc*sa + sb);
        }
        const float hvi = g_h[(size_t)(b*NN + i)*NC + f];
        const float x = hp + 0.2f * hvi;
        out[(size_t)(b*NN + i)*NC + f] = (x > 0.f) ? x : expm1f(x);
    }
}

// ---------------- launch ----------------
extern "C" void kernel_launch(void* const* d_in, const int* in_sizes, int n_in,
                              void* d_out, int out_size)
{
    int iText = 0, iW = 2, iA = 3;
    for (int i = 0; i < n_in; i++) {
        if (in_sizes[i] == NB*NN*NC) iText = i;
        else if (in_sizes[i] == NC*NC) iW = i;
        else if (in_sizes[i] == 2*NC) iA = i;
    }
    const float* text = (const float*)d_in[iText];
    const float* W    = (const float*)d_in[iW];
    const float* avec = (const float*)d_in[iA];
    float* out = (float*)d_out;

    gemm_kernel<<<dim3(NN/64, NB), 256>>>(text, W, avec);
    sort_kernel<<<NB, 1024>>>();
    chunk_kernel<<<dim3(NCH, NB), 128>>>();
    scan_kernel<<<dim3(NB, 16), 256>>>();
    expand_kernel<<<dim3(NCH, NB), 128>>>();
    query_kernel<<<dim3(NN/16, NB), 128>>>(out);
}

// round 6
// speedup vs baseline: 1.2509x; 1.1038x over previous
#include <cuda_runtime.h>
#include <math.h>
#include <float.h>

// Problem constants
#define NB 8
#define NN 2048
#define NC 128
#define NCH 128     // chunks per batch
#define CSZ 16      // chunk size (NCH*CSZ == NN)
#define NP (NN+1)   // prefix length 2049

// ---------------- scratch (device globals; no allocation) ----------------
__device__ float g_h[NB*NN*NC];        // h = text @ W
__device__ float g_s1[NB*NN];
__device__ float g_s2[NB*NN];
__device__ float g_s2s[NB*NN];         // sorted s2 (ascending, via rank scatter)
__device__ int   g_perm[NB*NN];        // permutation of sort
__device__ float g_wA[NB*NN];          // e^{s2s - m2}
__device__ float g_wB[NB*NN];          // e^{0.2(s2s - m2)}
__device__ float g_m2[NB];
__device__ float2 g_ch[NB*(NCH+1)*NC]; // chunk sums (x=A,y=B) -> exclusive prefixes; [NCH]=total
__device__ float g_paf[NB*NP];         // full scalar exclusive prefix of wA; [2048]=total
__device__ float g_pbf[NB*NP];
__device__ float2 g_P[NB*NP*NC];       // packed full vector prefixes (x=A, y=B)

// ---------------- f32x2 packed-FMA helpers (sm_103a FFMA2) ----------------
__device__ __forceinline__ unsigned long long pack2(float x, float y) {
    unsigned long long r;
    asm("mov.b64 %0, {%1, %2};" : "=l"(r) : "f"(x), "f"(y));
    return r;
}
__device__ __forceinline__ void unpack2(unsigned long long v, float& x, float& y) {
    asm("mov.b64 {%0, %1}, %2;" : "=f"(x), "=f"(y) : "l"(v));
}
__device__ __forceinline__ void ffma2(unsigned long long& d, unsigned long long a, unsigned long long b) {
    asm("fma.rn.f32x2 %0, %1, %2, %0;" : "+l"(d) : "l"(a), "l"(b));
}

// ---------------- Kernel 1: GEMM h = text@W (f32x2), fused s1/s2 ----------------
__global__ void __launch_bounds__(256) gemm_kernel(const float* __restrict__ A,
                                                   const float* __restrict__ W,
                                                   const float* __restrict__ avec)
{
    __shared__ float As[16][64];
    __shared__ float Bs[16][128];
    const int b  = blockIdx.y;
    const int m0 = blockIdx.x * 64;
    const int tid = threadIdx.x;
    const int tx = tid & 31;          // N dir: 32 * 4 = 128
    const int ty = tid >> 5;          // M dir: 8 * 8 = 64
    const float* Ab = A + (size_t)(b*NN + m0) * NC;

    unsigned long long acc2[4][4];
#pragma unroll
    for (int p = 0; p < 4; p++)
#pragma unroll
        for (int j = 0; j < 4; j++) acc2[p][j] = 0ull;

    const int ar = tid >> 2;          // 0..63
    const int ac = (tid & 3) * 4;     // 0,4,8,12

    for (int k0 = 0; k0 < 128; k0 += 16) {
        float4 av = *(const float4*)(Ab + (size_t)ar*NC + k0 + ac);
        As[ac+0][ar] = av.x; As[ac+1][ar] = av.y;
        As[ac+2][ar] = av.z; As[ac+3][ar] = av.w;
#pragma unroll
        for (int it = 0; it < 2; it++) {
            int idx = tid + 256*it;
            int brr = idx >> 5, bcc = (idx & 31) * 4;
            *(float4*)&Bs[brr][bcc] = *(const float4*)(W + (size_t)(k0+brr)*NC + bcc);
        }
        __syncthreads();
#pragma unroll
        for (int kk = 0; kk < 16; kk++) {
            float4 a03 = *(const float4*)&As[kk][ty*8];
            float4 a47 = *(const float4*)&As[kk][ty*8 + 4];
            float4 bv  = *(const float4*)&Bs[kk][tx*4];
            unsigned long long ap[4];
            ap[0] = pack2(a03.x, a03.y); ap[1] = pack2(a03.z, a03.w);
            ap[2] = pack2(a47.x, a47.y); ap[3] = pack2(a47.z, a47.w);
            unsigned long long bd[4];
            bd[0] = pack2(bv.x, bv.x); bd[1] = pack2(bv.y, bv.y);
            bd[2] = pack2(bv.z, bv.z); bd[3] = pack2(bv.w, bv.w);
#pragma unroll
            for (int p = 0; p < 4; p++)
#pragma unroll
                for (int j = 0; j < 4; j++) ffma2(acc2[p][j], ap[p], bd[j]);
        }
        __syncthreads();
    }

    float acc[8][4];
#pragma unroll
    for (int p = 0; p < 4; p++)
#pragma unroll
        for (int j = 0; j < 4; j++) unpack2(acc2[p][j], acc[2*p][j], acc[2*p+1][j]);

    float a1[4], a2[4];
#pragma unroll
    for (int j = 0; j < 4; j++) { a1[j] = avec[tx*4+j]; a2[j] = avec[128 + tx*4+j]; }

#pragma unroll
    for (int i = 0; i < 8; i++) {
        int row = m0 + ty*8 + i;
        float4 v = make_float4(acc[i][0], acc[i][1], acc[i][2], acc[i][3]);
        *(float4*)(g_h + (size_t)(b*NN + row)*NC + tx*4) = v;
        float d1 = acc[i][0]*a1[0] + acc[i][1]*a1[1] + acc[i][2]*a1[2] + acc[i][3]*a1[3];
        float d2 = acc[i][0]*a2[0] + acc[i][1]*a2[1] + acc[i][2]*a2[2] + acc[i][3]*a2[3];
#pragma unroll
        for (int off = 16; off > 0; off >>= 1) {
            d1 += __shfl_down_sync(0xffffffffu, d1, off);
            d2 += __shfl_down_sync(0xffffffffu, d2, off);
        }
        if (tx == 0) { g_s1[b*NN + row] = d1; g_s2[b*NN + row] = d2; }
    }
}

// ---------------- Kernel 2: rank-scatter "sort" (whole-chip parallel) ----------------
// grid (16, NB) x 128 threads; each thread owns one element, computes its rank
// by comparing against all 2048 keys (smem broadcast), scatters to rank position.
__global__ void __launch_bounds__(128) rank_kernel()
{
    __shared__ float keys[NN];
    __shared__ float red[4];
    const int b = blockIdx.y, tid = threadIdx.x;
    const int j = blockIdx.x * 128 + tid;

    for (int i = tid; i < NN; i += 128) keys[i] = g_s2[b*NN + i];
    __syncthreads();

    // block-wide max (m2) — every block computes it redundantly
    float mx = -FLT_MAX;
    for (int i = tid; i < NN; i += 128) mx = fmaxf(mx, keys[i]);
#pragma unroll
    for (int off = 16; off > 0; off >>= 1)
        mx = fmaxf(mx, __shfl_xor_sync(0xffffffffu, mx, off));
    if ((tid & 31) == 0) red[tid >> 5] = mx;
    __syncthreads();
    const float m2v = fmaxf(fmaxf(red[0], red[1]), fmaxf(red[2], red[3]));
    if (blockIdx.x == 0 && tid == 0) g_m2[b] = m2v;

    const float k = keys[j];
    int rank = 0;
#pragma unroll 8
    for (int jj = 0; jj < NN; jj++) {
        float kj = keys[jj];
        rank += (kj < k) || (kj == k && jj < j);
    }

    const float s = k - m2v;
    const int o = b*NN + rank;
    g_s2s[o]  = k;
    g_perm[o] = j;
    g_wA[o]   = expf(s);
    g_wB[o]   = expf(0.2f * s);
}

// ---------------- Kernel 3: scalar weight prefixes (per batch) ----------------
// grid NB x 128 threads; thread c owns chunk c (16 sorted weights)
__global__ void __launch_bounds__(128) spf_kernel()
{
    __shared__ float wtot[4], sa_sh[4], sb_sh[4];
    const int b = blockIdx.x, c = threadIdx.x;
    const int lane = c & 31, w = c >> 5;
    const int base = b*NN + c*CSZ;

    float va[CSZ], vb[CSZ];
    float sa = 0.f, sb = 0.f;
#pragma unroll
    for (int r = 0; r < CSZ; r++) {
        va[r] = g_wA[base + r];
        vb[r] = g_wB[base + r];
        sa += va[r]; sb += vb[r];
    }
    // warp inclusive scan of chunk sums
    float ia = sa, ib = sb;
#pragma unroll
    for (int off = 1; off < 32; off <<= 1) {
        float na = __shfl_up_sync(0xffffffffu, ia, off);
        float nb = __shfl_up_sync(0xffffffffu, ib, off);
        if (lane >= off) { ia += na; ib += nb; }
    }
    if (lane == 31) { sa_sh[w] = ia; sb_sh[w] = ib; }
    __syncthreads();
    float offA = 0.f, offB = 0.f;
#pragma unroll
    for (int ww = 0; ww < 4; ww++) {
        if (ww < w) { offA += sa_sh[ww]; offB += sb_sh[ww]; }
    }
    float ra = offA + ia - sa;   // exclusive prefix at chunk start
    float rb = offB + ib - sb;
#pragma unroll
    for (int r = 0; r < CSZ; r++) {
        g_paf[b*NP + c*CSZ + r] = ra;
        g_pbf[b*NP + c*CSZ + r] = rb;
        ra += va[r]; rb += vb[r];
    }
    if (c == 127) {
        g_paf[b*NP + NN] = ra;
        g_pbf[b*NP + NN] = rb;
    }
}

// ---------------- Kernel 4: vector chunk sums (per chunk, packed float2) ----------------
__global__ void __launch_bounds__(128) chunk_kernel()
{
    __shared__ int   js[CSZ];
    __shared__ float swa[CSZ], swb[CSZ];
    const int b = blockIdx.y, c = blockIdx.x, f = threadIdx.x;
    const int base = b*NN + c*CSZ;
    if (f < CSZ) {
        js[f]  = g_perm[base + f];
        swa[f] = g_wA[base + f];
        swb[f] = g_wB[base + f];
    }
    __syncthreads();
    float aA = 0.f, aB = 0.f;
#pragma unroll
    for (int r = 0; r < CSZ; r++) {
        float hv = g_h[(size_t)(b*NN + js[r])*NC + f];
        aA = fmaf(swa[r], hv, aA);
        aB = fmaf(swb[r], hv, aB);
    }
    g_ch[(size_t)(b*(NCH+1)+c)*NC + f] = make_float2(aA, aB);
}

// ---------------- Kernel 5: warp-parallel exclusive scan over 128 chunks ----------------
__global__ void __launch_bounds__(256) scan_kernel()
{
    const int b = blockIdx.x;
    const int w = threadIdx.x >> 5, lane = threadIdx.x & 31;
    const int f = blockIdx.y * 8 + w;
    const size_t base = (size_t)(b*(NCH+1))*NC + f;

    float2 v[4];
#pragma unroll
    for (int u = 0; u < 4; u++) v[u] = g_ch[base + (size_t)(lane*4+u)*NC];

    float ownA = (v[0].x + v[1].x) + (v[2].x + v[3].x);
    float ownB = (v[0].y + v[1].y) + (v[2].y + v[3].y);
    float sA = ownA, sB = ownB;
#pragma unroll
    for (int off = 1; off < 32; off <<= 1) {
        float nA = __shfl_up_sync(0xffffffffu, sA, off);
        float nB = __shfl_up_sync(0xffffffffu, sB, off);
        if (lane >= off) { sA += nA; sB += nB; }
    }
    float eA = sA - ownA, eB = sB - ownB;
#pragma unroll
    for (int u = 0; u < 4; u++) {
        float2 cur = v[u];
        g_ch[base + (size_t)(lane*4+u)*NC] = make_float2(eA, eB);
        eA += cur.x; eB += cur.y;
    }
    if (lane == 31) g_ch[base + (size_t)NCH*NC] = make_float2(sA, sB);
}

// ---------------- Kernel 6: expand full vector prefixes ----------------
__global__ void __launch_bounds__(128) expand_kernel()
{
    __shared__ float wa[CSZ], wb[CSZ];
    __shared__ int js[CSZ];
    const int b = blockIdx.y, c = blockIdx.x, f = threadIdx.x;
    const int base = b*NN + c*CSZ;
    if (f < CSZ) {
        wa[f] = g_wA[base + f];
        wb[f] = g_wB[base + f];
        js[f] = g_perm[base + f];
    }
    __syncthreads();

    float2 run = g_ch[(size_t)(b*(NCH+1)+c)*NC + f];
    float runA = run.x, runB = run.y;

    size_t p = (size_t)(b*NP + c*CSZ)*NC + f;
#pragma unroll
    for (int r = 0; r < CSZ; r++) {
        g_P[p] = make_float2(runA, runB);
        float hv = g_h[(size_t)(b*NN + js[r])*NC + f];
        runA = fmaf(wa[r], hv, runA);
        runB = fmaf(wb[r], hv, runB);
        p += NC;
    }
    if (c == NCH-1) g_P[p] = make_float2(runA, runB);  // index NN: grand totals
}

// ---------------- Kernel 7: per-query output ----------------
__global__ void __launch_bounds__(128) query_kernel(float* __restrict__ out)
{
    __shared__ float s2sh[NN];
    __shared__ int   ks[16];
    __shared__ float s1s[16];
    const int b = blockIdx.y, f = threadIdx.x;
    const int qbase = blockIdx.x * 16;
    for (int i = f; i < NN; i += 128) s2sh[i] = g_s2s[b*NN + i];
    __syncthreads();

    if (f < 16) {
        const int i = qbase + f;
        const float s1v = g_s1[b*NN + i];
        s1s[f] = s1v;
        const float t = -s1v;
        int k = 0;
#pragma unroll
        for (int st = 2048; st > 0; st >>= 1) {
            int nk = k + st;
            if (nk <= NN && s2sh[nk-1] <= t) k = nk;
        }
        ks[f] = k;
    }
    __syncthreads();

    const float m2v = g_m2[b];
    const float taf = g_P[(size_t)(b*NP + NN)*NC + f].x;
    const float tas = g_paf[b*NP + NN];

#pragma unroll 4
    for (int qi = 0; qi < 16; qi++) {
        const int i = qbase + qi;
        const int k = ks[qi];
        const float s1v = s1s[qi];
        const float2 Pk = g_P[(size_t)(b*NP + k)*NC + f];
        const float sap = g_paf[b*NP + k];
        const float sbp = g_pbf[b*NP + k];
        const float SA = taf - Pk.x, SB = Pk.y;
        const float sa = tas - sap, sb = sbp;
        const float u = s1v + m2v;
        float hp;
        if (u > 0.f) {
            float inv = expf(-0.8f * u);
            hp = (SA + inv*SB) / (sa + inv*sb);
        } else {
            float fc = expf(0.8f * u);
            hp = (fc*SA + SB) / (fc*sa + sb);
        }
        const float hvi = g_h[(size_t)(b*NN + i)*NC + f];
        const float x = hp + 0.2f * hvi;
        out[(size_t)(b*NN + i)*NC + f] = (x > 0.f) ? x : expm1f(x);
    }
}

// ---------------- launch ----------------
extern "C" void kernel_launch(void* const* d_in, const int* in_sizes, int n_in,
                              void* d_out, int out_size)
{
    int iText = 0, iW = 2, iA = 3;
    for (int i = 0; i < n_in; i++) {
        if (in_sizes[i] == NB*NN*NC) iText = i;
        else if (in_sizes[i] == NC*NC) iW = i;
        else if (in_sizes[i] == 2*NC) iA = i;
    }
    const float* text = (const float*)d_in[iText];
    const float* W    = (const float*)d_in[iW];
    const float* avec = (const float*)d_in[iA];
    float* out = (float*)d_out;

    gemm_kernel<<<dim3(NN/64, NB), 256>>>(text, W, avec);
    rank_kernel<<<dim3(16, NB), 128>>>();
    spf_kernel<<<NB, 128>>>();
    chunk_kernel<<<dim3(NCH, NB), 128>>>();
    scan_kernel<<<dim3(NB, 16), 256>>>();
    expand_kernel<<<dim3(NCH, NB), 128>>>();
    query_kernel<<<dim3(NN/16, NB), 128>>>(out);
}